// round 14
// baseline (speedup 1.0000x reference)
#include <cuda_runtime.h>
#include <cstdint>

#define NN 50000
#define NE 800000
#define D  128
#define NH 8
#define DH 16

// ---------------- scratch (static device globals; no allocation) -------------
__device__ float g_q[NN * D];
__device__ float g_k[NN * D];
__device__ float g_v[NN * D];
__device__ float g_agg[NN * D];
__device__ float g_s[NN * NH];     // softmax denominator (unshifted exp sums)
__device__ float g_mu[NN];         // LN mean
__device__ float g_rs[NN];         // LN rsqrt(var+eps)

// ---------------- L2 cache-policy helpers ------------------------------------
__device__ __forceinline__ uint64_t mk_policy_last() {
    uint64_t p;
    asm("createpolicy.fractional.L2::evict_last.b64 %0, 1.0;" : "=l"(p));
    return p;
}
__device__ __forceinline__ uint64_t mk_policy_first() {
    uint64_t p;
    asm("createpolicy.fractional.L2::evict_first.b64 %0, 1.0;" : "=l"(p));
    return p;
}
__device__ __forceinline__ float4 ldg_hint(const float4* p, uint64_t pol) {
    float4 r;
    asm("ld.global.nc.L2::cache_hint.v4.f32 {%0,%1,%2,%3}, [%4], %5;"
        : "=f"(r.x), "=f"(r.y), "=f"(r.z), "=f"(r.w) : "l"(p), "l"(pol));
    return r;
}
__device__ __forceinline__ void red_v4_hint(float* p, float a, float b,
                                            float c, float d, uint64_t pol) {
    asm volatile("red.global.add.L2::cache_hint.v4.f32 [%0], {%1,%2,%3,%4}, %5;"
                 :: "l"(p), "f"(a), "f"(b), "f"(c), "f"(d), "l"(pol) : "memory");
}
__device__ __forceinline__ void red_f32_hint(float* p, float v, uint64_t pol) {
    asm volatile("red.global.add.L2::cache_hint.f32 [%0], %1, %2;"
                 :: "l"(p), "f"(v), "l"(pol) : "memory");
}

// ---------------- fused LN stats + accumulator zeroing -----------------------
// One warp per node: LN mean/rstd; same block zeroes its 8 nodes' agg rows
// and g_s entries (replaces the separate init kernel).
__global__ void ln_init_kernel(const float* __restrict__ x) {
    int node = blockIdx.x * 8 + (threadIdx.x >> 5);
    int lane = threadIdx.x & 31;
    if (node < NN) {
        // zero this node's accumulators
        reinterpret_cast<float4*>(g_agg + (size_t)node * D)[lane] =
            make_float4(0.f, 0.f, 0.f, 0.f);
        if (lane < NH) g_s[node * NH + lane] = 0.0f;

        float4 v = reinterpret_cast<const float4*>(x + (size_t)node * D)[lane];
        float s  = v.x + v.y + v.z + v.w;
        float ss = v.x * v.x + v.y * v.y + v.z * v.z + v.w * v.w;
        #pragma unroll
        for (int o = 16; o; o >>= 1) {
            s  += __shfl_xor_sync(0xFFFFFFFFu, s, o);
            ss += __shfl_xor_sync(0xFFFFFFFFu, ss, o);
        }
        float mu  = s * (1.0f / D);
        float var = ss * (1.0f / D) - mu * mu;
        if (lane == 0) {
            g_mu[node] = mu;
            g_rs[node] = rsqrtf(var + 1e-5f);
        }
    }
}

// ---------------- TF32 tensor-core GEMM: C = LN(A)(M x 128) @ W(128 x Ntot) --
// MODE 0: A = x (param) with LN applied inline, out -> q/k/v
// MODE 1: A = g_agg (device symbol, resolved device-side) scaled by
//         1/max(s,1e-16) per row+head, out = x + A@W + out_b
__device__ __forceinline__ unsigned f2tf(float f) {
    unsigned u;
    asm("cvt.rna.tf32.f32 %0, %1;" : "=r"(u) : "f"(f));
    return u;
}

template <int MODE>
__global__ __launch_bounds__(256, 2)
void gemm_tc(const float* __restrict__ Ain,
             const float* __restrict__ W,
             const float* __restrict__ bias,
             const float* __restrict__ lng,
             const float* __restrict__ lnb,
             const float* __restrict__ xres,
             float* __restrict__ out,
             int Ntot) {
    __shared__ unsigned As[128][36];   // [m][k-chunk], stride 36
    __shared__ unsigned Bs[32][136];   // [k][n],       stride 136

    const float* A = (MODE == 0) ? Ain : g_agg;

    int tid  = threadIdx.x;
    int m0   = blockIdx.y * 128;
    int n0   = blockIdx.x * 128;
    int wid  = tid >> 5, lane = tid & 31;
    int wm   = (wid >> 1) * 32;
    int wn   = (wid & 1) * 64;
    int g    = lane >> 2, tg = lane & 3;

    float acc[2][8][4];
    #pragma unroll
    for (int mi = 0; mi < 2; mi++)
        #pragma unroll
        for (int ni = 0; ni < 8; ni++)
            #pragma unroll
            for (int c = 0; c < 4; c++) acc[mi][ni][c] = 0.0f;

    for (int kk = 0; kk < 128; kk += 32) {
        {
            int row  = tid >> 1, half = tid & 1;
            int grow = m0 + row;
            float mu = 0.f, rs = 0.f, inv = 1.0f;
            if (grow < NN) {
                if (MODE == 0) { mu = g_mu[grow]; rs = g_rs[grow]; }
                else inv = 1.0f / fmaxf(g_s[grow * NH + (kk >> 4) + half], 1e-16f);
            }
            #pragma unroll
            for (int j = 0; j < 4; j++) {
                int c = kk + half * 16 + j * 4;
                float4 a = make_float4(0.f, 0.f, 0.f, 0.f);
                if (grow < NN)
                    a = *reinterpret_cast<const float4*>(A + (size_t)grow * D + c);
                if (MODE == 0) {
                    float4 gj = *reinterpret_cast<const float4*>(lng + c);
                    float4 bj = *reinterpret_cast<const float4*>(lnb + c);
                    a.x = (a.x - mu) * rs * gj.x + bj.x;
                    a.y = (a.y - mu) * rs * gj.y + bj.y;
                    a.z = (a.z - mu) * rs * gj.z + bj.z;
                    a.w = (a.w - mu) * rs * gj.w + bj.w;
                } else {
                    a.x *= inv; a.y *= inv; a.z *= inv; a.w *= inv;
                }
                uint4 u = make_uint4(f2tf(a.x), f2tf(a.y), f2tf(a.z), f2tf(a.w));
                *reinterpret_cast<uint4*>(&As[row][half * 16 + j * 4]) = u;
            }
        }
        {
            int krow = tid >> 3, cg = tid & 7;
            #pragma unroll
            for (int j = 0; j < 4; j++) {
                float4 w = *reinterpret_cast<const float4*>(
                    W + (size_t)(kk + krow) * Ntot + n0 + cg * 16 + j * 4);
                uint4 u = make_uint4(f2tf(w.x), f2tf(w.y), f2tf(w.z), f2tf(w.w));
                *reinterpret_cast<uint4*>(&Bs[krow][cg * 16 + j * 4]) = u;
            }
        }
        __syncthreads();
        #pragma unroll
        for (int ks = 0; ks < 4; ks++) {
            unsigned af[2][4];
            #pragma unroll
            for (int mi = 0; mi < 2; mi++) {
                int r = wm + mi * 16 + g;
                int kc = ks * 8 + tg;
                af[mi][0] = As[r][kc];
                af[mi][1] = As[r + 8][kc];
                af[mi][2] = As[r][kc + 4];
                af[mi][3] = As[r + 8][kc + 4];
            }
            unsigned bf[8][2];
            #pragma unroll
            for (int ni = 0; ni < 8; ni++) {
                int nc = wn + ni * 8 + g;
                bf[ni][0] = Bs[ks * 8 + tg][nc];
                bf[ni][1] = Bs[ks * 8 + tg + 4][nc];
            }
            #pragma unroll
            for (int mi = 0; mi < 2; mi++)
                #pragma unroll
                for (int ni = 0; ni < 8; ni++) {
                    asm volatile(
                        "mma.sync.aligned.m16n8k8.row.col.f32.tf32.tf32.f32 "
                        "{%0,%1,%2,%3},{%4,%5,%6,%7},{%8,%9},{%0,%1,%2,%3};"
                        : "+f"(acc[mi][ni][0]), "+f"(acc[mi][ni][1]),
                          "+f"(acc[mi][ni][2]), "+f"(acc[mi][ni][3])
                        : "r"(af[mi][0]), "r"(af[mi][1]),
                          "r"(af[mi][2]), "r"(af[mi][3]),
                          "r"(bf[ni][0]), "r"(bf[ni][1]));
                }
        }
        __syncthreads();
    }

    int part = n0 >> 7;
    float* dstq = (part == 0) ? g_q : (part == 1) ? g_k : g_v;
    #pragma unroll
    for (int mi = 0; mi < 2; mi++) {
        #pragma unroll
        for (int ni = 0; ni < 8; ni++) {
            int col = wn + ni * 8 + tg * 2;
            float b0 = bias[n0 + col], b1 = bias[n0 + col + 1];
            #pragma unroll
            for (int half = 0; half < 2; half++) {
                int row = m0 + wm + mi * 16 + g + half * 8;
                if (row >= NN) continue;
                float o0 = acc[mi][ni][half * 2 + 0] + b0;
                float o1 = acc[mi][ni][half * 2 + 1] + b1;
                if (MODE == 0) {
                    *reinterpret_cast<float2*>(dstq + (size_t)row * D + col) =
                        make_float2(o0, o1);
                } else {
                    float2 xr = *reinterpret_cast<const float2*>(
                        xres + (size_t)row * D + col);
                    *reinterpret_cast<float2*>(out + (size_t)row * D + col) =
                        make_float2(xr.x + o0, xr.y + o1);
                }
            }
        }
    }
}

// ---------------- fused edge pass: warp-per-edge, 2 edges/warp, src-split ----
// Processes only edges whose src is in [lo, hi): per-pass k/v working set
// halves (38.5MB), keeping q+k/v+streaming-ea within L2 capacity. Reductions
// (g_agg red.v4 and g_s scalar red) carry an evict_last policy so partial
// sums aren't thrashed to DRAM between touches by the ea stream.
__global__ __launch_bounds__(256)
void edge_kernel(const float* __restrict__ ea, const int* __restrict__ ei,
                 int lo, int hi) {
    int warp = blockIdx.x * 8 + (threadIdx.x >> 5);
    int lane = threadIdx.x & 31;
    int e0 = warp * 2, e1 = e0 + 1;
    if (e0 >= NE) return;

    uint64_t pl = mk_policy_last();
    uint64_t pf = mk_policy_first();

    int src0 = __ldg(ei + e0),  dst0 = __ldg(ei + NE + e0);
    int src1 = 0, dst1 = 0;
    bool ok1 = (e1 < NE);
    if (ok1) { src1 = __ldg(ei + e1); dst1 = __ldg(ei + NE + e1); }
    bool ok0 = (unsigned)src0 < NN && (unsigned)dst0 < NN
               && src0 >= lo && src0 < hi;
    ok1 = ok1 && (unsigned)src1 < NN && (unsigned)dst1 < NN
               && src1 >= lo && src1 < hi;
    if (!ok0 && !ok1) return;

    float4 q0 = make_float4(0,0,0,0), k0 = q0, a0 = q0, v0 = q0;
    float4 q1 = q0, k1 = q0, a1 = q0, v1 = q0;
    if (ok0) {
        q0 = ldg_hint(reinterpret_cast<const float4*>(g_q + (size_t)dst0 * D) + lane, pl);
        k0 = ldg_hint(reinterpret_cast<const float4*>(g_k + (size_t)src0 * D) + lane, pl);
        a0 = ldg_hint(reinterpret_cast<const float4*>(ea + (size_t)e0 * D) + lane, pf);
        v0 = ldg_hint(reinterpret_cast<const float4*>(g_v + (size_t)src0 * D) + lane, pl);
    }
    if (ok1) {
        q1 = ldg_hint(reinterpret_cast<const float4*>(g_q + (size_t)dst1 * D) + lane, pl);
        k1 = ldg_hint(reinterpret_cast<const float4*>(g_k + (size_t)src1 * D) + lane, pl);
        a1 = ldg_hint(reinterpret_cast<const float4*>(ea + (size_t)e1 * D) + lane, pf);
        v1 = ldg_hint(reinterpret_cast<const float4*>(g_v + (size_t)src1 * D) + lane, pl);
    }

    float s0 = q0.x * (k0.x + a0.x) + q0.y * (k0.y + a0.y)
             + q0.z * (k0.z + a0.z) + q0.w * (k0.w + a0.w);
    float s1 = q1.x * (k1.x + a1.x) + q1.y * (k1.y + a1.y)
             + q1.z * (k1.z + a1.z) + q1.w * (k1.w + a1.w);
    s0 += __shfl_xor_sync(0xFFFFFFFFu, s0, 1);
    s0 += __shfl_xor_sync(0xFFFFFFFFu, s0, 2);
    s1 += __shfl_xor_sync(0xFFFFFFFFu, s1, 1);
    s1 += __shfl_xor_sync(0xFFFFFFFFu, s1, 2);

    float ev0 = __expf(s0 * 0.25f);   // 0.25 = 1/sqrt(DH)
    float ev1 = __expf(s1 * 0.25f);

    if (ok0) {
        if ((lane & 3) == 0)
            red_f32_hint(&g_s[dst0 * NH + (lane >> 2)], ev0, pl);
        red_v4_hint(g_agg + (size_t)dst0 * D + lane * 4,
                    ev0 * v0.x, ev0 * v0.y, ev0 * v0.z, ev0 * v0.w, pl);
    }
    if (ok1) {
        if ((lane & 3) == 0)
            red_f32_hint(&g_s[dst1 * NH + (lane >> 2)], ev1, pl);
        red_v4_hint(g_agg + (size_t)dst1 * D + lane * 4,
                    ev1 * v1.x, ev1 * v1.y, ev1 * v1.z, ev1 * v1.w, pl);
    }
}

// ---------------- launcher ---------------------------------------------------
extern "C" void kernel_launch(void* const* d_in, const int* in_sizes, int n_in,
                              void* d_out, int out_size) {
    const float* x     = (const float*)d_in[0];
    const float* ea    = (const float*)d_in[1];
    const float* qkv_w = (const float*)d_in[2];
    const float* qkv_b = (const float*)d_in[3];
    const float* out_w = (const float*)d_in[4];
    const float* out_b = (const float*)d_in[5];
    const float* ln_g  = (const float*)d_in[6];
    const float* ln_b  = (const float*)d_in[7];
    const int*   ei    = (const int*)d_in[8];
    float* out = (float*)d_out;

    int edge_blocks = (NE / 2 + 7) / 8;
    ln_init_kernel<<<(NN + 7) / 8, 256>>>(x);
    gemm_tc<0><<<dim3(3, (NN + 127) / 128), 256>>>(x, qkv_w, qkv_b, ln_g, ln_b,
                                                   nullptr, nullptr, 384);
    edge_kernel<<<edge_blocks, 256>>>(ea, ei, 0, NN / 2);
    edge_kernel<<<edge_blocks, 256>>>(ea, ei, NN / 2, NN);
    gemm_tc<1><<<dim3(1, (NN + 127) / 128), 256>>>(nullptr, out_w, out_b, nullptr,
                                                   nullptr, x, out, 128);
}

// round 15
// speedup vs baseline: 1.0928x; 1.0928x over previous
#include <cuda_runtime.h>
#include <cstdint>

#define NN 50000
#define NE 800000
#define D  128
#define NH 8
#define DH 16

// ---------------- scratch (static device globals; no allocation) -------------
__device__ float g_q[NN * D];
__device__ float g_k[NN * D];
__device__ float g_v[NN * D];
__device__ float g_agg[NN * D];
__device__ float g_s[NN * NH];     // softmax denominator (unshifted exp sums)
__device__ float g_mu[NN];         // LN mean
__device__ float g_rs[NN];         // LN rsqrt(var+eps)

// ---------------- L2 cache-policy helpers ------------------------------------
__device__ __forceinline__ uint64_t mk_policy_last() {
    uint64_t p;
    asm("createpolicy.fractional.L2::evict_last.b64 %0, 1.0;" : "=l"(p));
    return p;
}
__device__ __forceinline__ uint64_t mk_policy_first() {
    uint64_t p;
    asm("createpolicy.fractional.L2::evict_first.b64 %0, 1.0;" : "=l"(p));
    return p;
}
__device__ __forceinline__ float4 ldg_hint(const float4* p, uint64_t pol) {
    float4 r;
    asm("ld.global.nc.L2::cache_hint.v4.f32 {%0,%1,%2,%3}, [%4], %5;"
        : "=f"(r.x), "=f"(r.y), "=f"(r.z), "=f"(r.w) : "l"(p), "l"(pol));
    return r;
}
__device__ __forceinline__ void red_v4_hint(float* p, float a, float b,
                                            float c, float d, uint64_t pol) {
    asm volatile("red.global.add.L2::cache_hint.v4.f32 [%0], {%1,%2,%3,%4}, %5;"
                 :: "l"(p), "f"(a), "f"(b), "f"(c), "f"(d), "l"(pol) : "memory");
}
__device__ __forceinline__ void red_f32_hint(float* p, float v, uint64_t pol) {
    asm volatile("red.global.add.L2::cache_hint.f32 [%0], %1, %2;"
                 :: "l"(p), "f"(v), "l"(pol) : "memory");
}

// ---------------- fused LN stats + accumulator zeroing -----------------------
__global__ void ln_init_kernel(const float* __restrict__ x) {
    int node = blockIdx.x * 8 + (threadIdx.x >> 5);
    int lane = threadIdx.x & 31;
    if (node < NN) {
        reinterpret_cast<float4*>(g_agg + (size_t)node * D)[lane] =
            make_float4(0.f, 0.f, 0.f, 0.f);
        if (lane < NH) g_s[node * NH + lane] = 0.0f;

        float4 v = reinterpret_cast<const float4*>(x + (size_t)node * D)[lane];
        float s  = v.x + v.y + v.z + v.w;
        float ss = v.x * v.x + v.y * v.y + v.z * v.z + v.w * v.w;
        #pragma unroll
        for (int o = 16; o; o >>= 1) {
            s  += __shfl_xor_sync(0xFFFFFFFFu, s, o);
            ss += __shfl_xor_sync(0xFFFFFFFFu, ss, o);
        }
        float mu  = s * (1.0f / D);
        float var = ss * (1.0f / D) - mu * mu;
        if (lane == 0) {
            g_mu[node] = mu;
            g_rs[node] = rsqrtf(var + 1e-5f);
        }
    }
}

// ---------------- TF32 tensor-core GEMM: C = LN(A)(M x 128) @ W(128 x Ntot) --
// MODE 0: A = x (param) with LN applied inline, out -> q/k/v
// MODE 1: A = g_agg (device symbol, resolved device-side) scaled by
//         1/max(s,1e-16) per row+head, out = x + A@W + out_b
__device__ __forceinline__ unsigned f2tf(float f) {
    unsigned u;
    asm("cvt.rna.tf32.f32 %0, %1;" : "=r"(u) : "f"(f));
    return u;
}

template <int MODE>
__global__ __launch_bounds__(256, 2)
void gemm_tc(const float* __restrict__ Ain,
             const float* __restrict__ W,
             const float* __restrict__ bias,
             const float* __restrict__ lng,
             const float* __restrict__ lnb,
             const float* __restrict__ xres,
             float* __restrict__ out,
             int Ntot) {
    __shared__ unsigned As[128][36];   // [m][k-chunk], stride 36
    __shared__ unsigned Bs[32][136];   // [k][n],       stride 136

    const float* A = (MODE == 0) ? Ain : g_agg;

    int tid  = threadIdx.x;
    int m0   = blockIdx.y * 128;
    int n0   = blockIdx.x * 128;
    int wid  = tid >> 5, lane = tid & 31;
    int wm   = (wid >> 1) * 32;
    int wn   = (wid & 1) * 64;
    int g    = lane >> 2, tg = lane & 3;

    float acc[2][8][4];
    #pragma unroll
    for (int mi = 0; mi < 2; mi++)
        #pragma unroll
        for (int ni = 0; ni < 8; ni++)
            #pragma unroll
            for (int c = 0; c < 4; c++) acc[mi][ni][c] = 0.0f;

    for (int kk = 0; kk < 128; kk += 32) {
        {
            int row  = tid >> 1, half = tid & 1;
            int grow = m0 + row;
            float mu = 0.f, rs = 0.f, inv = 1.0f;
            if (grow < NN) {
                if (MODE == 0) { mu = g_mu[grow]; rs = g_rs[grow]; }
                else inv = 1.0f / fmaxf(g_s[grow * NH + (kk >> 4) + half], 1e-16f);
            }
            #pragma unroll
            for (int j = 0; j < 4; j++) {
                int c = kk + half * 16 + j * 4;
                float4 a = make_float4(0.f, 0.f, 0.f, 0.f);
                if (grow < NN)
                    a = *reinterpret_cast<const float4*>(A + (size_t)grow * D + c);
                if (MODE == 0) {
                    float4 gj = *reinterpret_cast<const float4*>(lng + c);
                    float4 bj = *reinterpret_cast<const float4*>(lnb + c);
                    a.x = (a.x - mu) * rs * gj.x + bj.x;
                    a.y = (a.y - mu) * rs * gj.y + bj.y;
                    a.z = (a.z - mu) * rs * gj.z + bj.z;
                    a.w = (a.w - mu) * rs * gj.w + bj.w;
                } else {
                    a.x *= inv; a.y *= inv; a.z *= inv; a.w *= inv;
                }
                uint4 u = make_uint4(f2tf(a.x), f2tf(a.y), f2tf(a.z), f2tf(a.w));
                *reinterpret_cast<uint4*>(&As[row][half * 16 + j * 4]) = u;
            }
        }
        {
            int krow = tid >> 3, cg = tid & 7;
            #pragma unroll
            for (int j = 0; j < 4; j++) {
                float4 w = *reinterpret_cast<const float4*>(
                    W + (size_t)(kk + krow) * Ntot + n0 + cg * 16 + j * 4);
                uint4 u = make_uint4(f2tf(w.x), f2tf(w.y), f2tf(w.z), f2tf(w.w));
                *reinterpret_cast<uint4*>(&Bs[krow][cg * 16 + j * 4]) = u;
            }
        }
        __syncthreads();
        #pragma unroll
        for (int ks = 0; ks < 4; ks++) {
            unsigned af[2][4];
            #pragma unroll
            for (int mi = 0; mi < 2; mi++) {
                int r = wm + mi * 16 + g;
                int kc = ks * 8 + tg;
                af[mi][0] = As[r][kc];
                af[mi][1] = As[r + 8][kc];
                af[mi][2] = As[r][kc + 4];
                af[mi][3] = As[r + 8][kc + 4];
            }
            unsigned bf[8][2];
            #pragma unroll
            for (int ni = 0; ni < 8; ni++) {
                int nc = wn + ni * 8 + g;
                bf[ni][0] = Bs[ks * 8 + tg][nc];
                bf[ni][1] = Bs[ks * 8 + tg + 4][nc];
            }
            #pragma unroll
            for (int mi = 0; mi < 2; mi++)
                #pragma unroll
                for (int ni = 0; ni < 8; ni++) {
                    asm volatile(
                        "mma.sync.aligned.m16n8k8.row.col.f32.tf32.tf32.f32 "
                        "{%0,%1,%2,%3},{%4,%5,%6,%7},{%8,%9},{%0,%1,%2,%3};"
                        : "+f"(acc[mi][ni][0]), "+f"(acc[mi][ni][1]),
                          "+f"(acc[mi][ni][2]), "+f"(acc[mi][ni][3])
                        : "r"(af[mi][0]), "r"(af[mi][1]),
                          "r"(af[mi][2]), "r"(af[mi][3]),
                          "r"(bf[ni][0]), "r"(bf[ni][1]));
                }
        }
        __syncthreads();
    }

    int part = n0 >> 7;
    float* dstq = (part == 0) ? g_q : (part == 1) ? g_k : g_v;
    #pragma unroll
    for (int mi = 0; mi < 2; mi++) {
        #pragma unroll
        for (int ni = 0; ni < 8; ni++) {
            int col = wn + ni * 8 + tg * 2;
            float b0 = bias[n0 + col], b1 = bias[n0 + col + 1];
            #pragma unroll
            for (int half = 0; half < 2; half++) {
                int row = m0 + wm + mi * 16 + g + half * 8;
                if (row >= NN) continue;
                float o0 = acc[mi][ni][half * 2 + 0] + b0;
                float o1 = acc[mi][ni][half * 2 + 1] + b1;
                if (MODE == 0) {
                    *reinterpret_cast<float2*>(dstq + (size_t)row * D + col) =
                        make_float2(o0, o1);
                } else {
                    float2 xr = *reinterpret_cast<const float2*>(
                        xres + (size_t)row * D + col);
                    *reinterpret_cast<float2*>(out + (size_t)row * D + col) =
                        make_float2(xr.x + o0, xr.y + o1);
                }
            }
        }
    }
}

// ---------------- fused edge pass: warp-per-edge, 2 edges/warp, SINGLE pass --
// Lane l owns float4 l of the 512-byte node row; all 8 gathers issued before
// compute. q/k/v loads + both reductions carry an evict_last L2 policy so the
// working set and partial sums stay L2-resident against the streaming ea
// (evict_first). Head h = lane>>2; dot reduced over the 4-lane quad with 2
// SHFL.BFLY. Softmax without max-shift (scores ~N(0,2), no fp32 hazard).
__global__ __launch_bounds__(256)
void edge_kernel(const float* __restrict__ ea, const int* __restrict__ ei) {
    int warp = blockIdx.x * 8 + (threadIdx.x >> 5);
    int lane = threadIdx.x & 31;
    int e0 = warp * 2, e1 = e0 + 1;
    if (e0 >= NE) return;

    uint64_t pl = mk_policy_last();
    uint64_t pf = mk_policy_first();

    int src0 = __ldg(ei + e0),  dst0 = __ldg(ei + NE + e0);
    int src1 = 0, dst1 = 0;
    bool ok1 = (e1 < NE);
    if (ok1) { src1 = __ldg(ei + e1); dst1 = __ldg(ei + NE + e1); }
    bool ok0 = (unsigned)src0 < NN && (unsigned)dst0 < NN;
    ok1 = ok1 && (unsigned)src1 < NN && (unsigned)dst1 < NN;

    float4 q0 = make_float4(0,0,0,0), k0 = q0, a0 = q0, v0 = q0;
    float4 q1 = q0, k1 = q0, a1 = q0, v1 = q0;
    if (ok0) {
        q0 = ldg_hint(reinterpret_cast<const float4*>(g_q + (size_t)dst0 * D) + lane, pl);
        k0 = ldg_hint(reinterpret_cast<const float4*>(g_k + (size_t)src0 * D) + lane, pl);
        a0 = ldg_hint(reinterpret_cast<const float4*>(ea + (size_t)e0 * D) + lane, pf);
        v0 = ldg_hint(reinterpret_cast<const float4*>(g_v + (size_t)src0 * D) + lane, pl);
    }
    if (ok1) {
        q1 = ldg_hint(reinterpret_cast<const float4*>(g_q + (size_t)dst1 * D) + lane, pl);
        k1 = ldg_hint(reinterpret_cast<const float4*>(g_k + (size_t)src1 * D) + lane, pl);
        a1 = ldg_hint(reinterpret_cast<const float4*>(ea + (size_t)e1 * D) + lane, pf);
        v1 = ldg_hint(reinterpret_cast<const float4*>(g_v + (size_t)src1 * D) + lane, pl);
    }

    float s0 = q0.x * (k0.x + a0.x) + q0.y * (k0.y + a0.y)
             + q0.z * (k0.z + a0.z) + q0.w * (k0.w + a0.w);
    float s1 = q1.x * (k1.x + a1.x) + q1.y * (k1.y + a1.y)
             + q1.z * (k1.z + a1.z) + q1.w * (k1.w + a1.w);
    s0 += __shfl_xor_sync(0xFFFFFFFFu, s0, 1);
    s0 += __shfl_xor_sync(0xFFFFFFFFu, s0, 2);
    s1 += __shfl_xor_sync(0xFFFFFFFFu, s1, 1);
    s1 += __shfl_xor_sync(0xFFFFFFFFu, s1, 2);

    float ev0 = __expf(s0 * 0.25f);   // 0.25 = 1/sqrt(DH)
    float ev1 = __expf(s1 * 0.25f);

    if (ok0) {
        if ((lane & 3) == 0)
            red_f32_hint(&g_s[dst0 * NH + (lane >> 2)], ev0, pl);
        red_v4_hint(g_agg + (size_t)dst0 * D + lane * 4,
                    ev0 * v0.x, ev0 * v0.y, ev0 * v0.z, ev0 * v0.w, pl);
    }
    if (ok1) {
        if ((lane & 3) == 0)
            red_f32_hint(&g_s[dst1 * NH + (lane >> 2)], ev1, pl);
        red_v4_hint(g_agg + (size_t)dst1 * D + lane * 4,
                    ev1 * v1.x, ev1 * v1.y, ev1 * v1.z, ev1 * v1.w, pl);
    }
}

// ---------------- launcher ---------------------------------------------------
extern "C" void kernel_launch(void* const* d_in, const int* in_sizes, int n_in,
                              void* d_out, int out_size) {
    const float* x     = (const float*)d_in[0];
    const float* ea    = (const float*)d_in[1];
    const float* qkv_w = (const float*)d_in[2];
    const float* qkv_b = (const float*)d_in[3];
    const float* out_w = (const float*)d_in[4];
    const float* out_b = (const float*)d_in[5];
    const float* ln_g  = (const float*)d_in[6];
    const float* ln_b  = (const float*)d_in[7];
    const int*   ei    = (const int*)d_in[8];
    float* out = (float*)d_out;

    ln_init_kernel<<<(NN + 7) / 8, 256>>>(x);
    gemm_tc<0><<<dim3(3, (NN + 127) / 128), 256>>>(x, qkv_w, qkv_b, ln_g, ln_b,
                                                   nullptr, nullptr, 384);
    edge_kernel<<<(NE / 2 + 7) / 8, 256>>>(ea, ei);
    gemm_tc<1><<<dim3(1, (NN + 127) / 128), 256>>>(nullptr, out_w, out_b, nullptr,
                                                   nullptr, x, out, 128);
}